// round 3
// baseline (speedup 1.0000x reference)
#include <cuda_runtime.h>
#include <cstdint>
#include <cstddef>

#define B_    64
#define S_    256
#define H_    16
#define D_    256
#define HIDN  4096
#define M_    (B_*S_)          // 16384 tokens
#define JVALID 192             // S - WINDOW
#define SCALE_ 0.0625f         // 1/sqrt(256)

#define TS 132                 // smem tile stride (128 + 4 pad)

// Scratch: Q, K1, K2, V each laid out [b][h][s][d] (65536 floats per (b,h))
__device__ float g_scratch[(size_t)4 * M_ * HIDN];   // 1 GiB
__device__ float g_wv[(size_t)HIDN * HIDN];          // wv1 + wv2
__device__ float g_bv[HIDN];

// ---------------------------------------------------------------------------
// Kernel 0: combine V weights/bias (P@v1 + P@v2 == P@(v1+v2))
// ---------------------------------------------------------------------------
__global__ void combine_wv(const float* __restrict__ wv1, const float* __restrict__ wv2,
                           const float* __restrict__ bv1, const float* __restrict__ bv2) {
    size_t i = (size_t)blockIdx.x * blockDim.x + threadIdx.x;
    if (i < (size_t)HIDN * HIDN) g_wv[i] = wv1[i] + wv2[i];
    if (i < HIDN)                g_bv[i] = bv1[i] + bv2[i];
}

// ---------------------------------------------------------------------------
// Shared micro-GEMM helpers (128x128 tile, K-chunk 16, 256 threads, 8x8/thread)
// ---------------------------------------------------------------------------

// Load a [128 rows x 16 k] tile where k is the contiguous axis of src
// (row stride = ld), storing TRANSPOSED into Ts[k*TS + row].
__device__ __forceinline__ void load_tileT(float* Ts, const float* src, int ld, int tid) {
#pragma unroll
    for (int it = 0; it < 2; it++) {
        int idx = tid + it * 256;          // 512 float4s total
        int row = idx >> 2;
        int k4  = (idx & 3) << 2;
        float4 v = *(const float4*)(src + (size_t)row * ld + k4);
        Ts[(k4 + 0) * TS + row] = v.x;
        Ts[(k4 + 1) * TS + row] = v.y;
        Ts[(k4 + 2) * TS + row] = v.z;
        Ts[(k4 + 3) * TS + row] = v.w;
    }
}

// Load a [16 k x 128 n] tile where n is the contiguous axis of src
// (k-row stride = ld), storing into Ts[k*TS + n].
__device__ __forceinline__ void load_tileN(float* Ts, const float* src, int ld, int tid) {
#pragma unroll
    for (int it = 0; it < 2; it++) {
        int idx = tid + it * 256;          // 512 float4s total
        int k  = idx >> 5;
        int n4 = (idx & 31) << 2;
        *(float4*)(Ts + k * TS + n4) = *(const float4*)(src + (size_t)k * ld + n4);
    }
}

__device__ __forceinline__ void mm16(const float* As, const float* Bs,
                                     float acc[8][8], int ty, int tx) {
#pragma unroll
    for (int k = 0; k < 16; k++) {
        float a[8], b[8];
        *(float4*)&a[0] = *(const float4*)(As + k * TS + ty * 8);
        *(float4*)&a[4] = *(const float4*)(As + k * TS + ty * 8 + 4);
        *(float4*)&b[0] = *(const float4*)(Bs + k * TS + tx * 8);
        *(float4*)&b[4] = *(const float4*)(Bs + k * TS + tx * 8 + 4);
#pragma unroll
        for (int i = 0; i < 8; i++)
#pragma unroll
            for (int j = 0; j < 8; j++)
                acc[i][j] += a[i] * b[j];
    }
}

// ---------------------------------------------------------------------------
// Kernel 1: fused 4-way projection GEMM  Y = X @ W^T + b
// grid = (32 n-tiles, 128 m-tiles, 4 projections); z: 0=Q 1=K1 2=K2 3=V
// Output written directly in [b][h][s][d] layout into g_scratch.
// ---------------------------------------------------------------------------
__global__ __launch_bounds__(256, 2) void proj_gemm(
    const float* __restrict__ X,
    const float* __restrict__ wq, const float* __restrict__ wk1, const float* __restrict__ wk2,
    const float* __restrict__ bq, const float* __restrict__ bk1, const float* __restrict__ bk2) {
    __shared__ float As[16 * TS];
    __shared__ float Bs[16 * TS];

    int tid = threadIdx.x;
    int tx = tid & 15, ty = tid >> 4;
    int z = blockIdx.z;

    const float* W  = (z == 0) ? wq : (z == 1) ? wk1 : (z == 2) ? wk2 : g_wv;
    const float* bb = (z == 0) ? bq : (z == 1) ? bk1 : (z == 2) ? bk2 : g_bv;

    int rbase = blockIdx.y * 128;   // token rows
    int cbase = blockIdx.x * 128;   // output feature cols

    float acc[8][8];
#pragma unroll
    for (int i = 0; i < 8; i++)
#pragma unroll
        for (int j = 0; j < 8; j++) acc[i][j] = 0.f;

    for (int kt = 0; kt < HIDN / 16; kt++) {
        load_tileT(As, X + (size_t)rbase * HIDN + kt * 16, HIDN, tid);
        load_tileT(Bs, W + (size_t)cbase * HIDN + kt * 16, HIDN, tid);
        __syncthreads();
        mm16(As, Bs, acc, ty, tx);
        __syncthreads();
    }

    // Epilogue: bias + scatter into [b][h][s][d]
    int b  = rbase >> 8;
    int s0 = (rbase & 255);
    int h  = cbase >> 8;
    int d0 = (cbase & 255) + tx * 8;
    float4 bvA = *(const float4*)(bb + cbase + tx * 8);
    float4 bvB = *(const float4*)(bb + cbase + tx * 8 + 4);
    float* outp = g_scratch + (size_t)z * ((size_t)M_ * HIDN)
                + (size_t)(b * H_ + h) * (S_ * D_);
#pragma unroll
    for (int i = 0; i < 8; i++) {
        int s = s0 + ty * 8 + i;
        float4 o0 = make_float4(acc[i][0] + bvA.x, acc[i][1] + bvA.y,
                                acc[i][2] + bvA.z, acc[i][3] + bvA.w);
        float4 o1 = make_float4(acc[i][4] + bvB.x, acc[i][5] + bvB.y,
                                acc[i][6] + bvB.z, acc[i][7] + bvB.w);
        *(float4*)(outp + (size_t)s * D_ + d0)     = o0;
        *(float4*)(outp + (size_t)s * D_ + d0 + 4) = o1;
    }
}

// ---------------------------------------------------------------------------
// Kernel 2: attention per (b, h, q-half). All three chained GEMMs on-chip.
//   s1     = q @ k1^T                (128 x 256)
//   scores = (s1 @ k2^T) * SCALE     (128 x 256), cols >= 192 masked
//   P      = softmax(scores[:, :192])
//   ctx    = P @ V[0:192, :]         (128 x 256)
// Dynamic smem: P(128x256) + SC(128x128) + As + Bs = 213504 B
// ---------------------------------------------------------------------------
__global__ __launch_bounds__(256) void attn_kernel(float* __restrict__ out) {
    extern __shared__ float sm[];
    float* P  = sm;                        // 32768 floats
    float* SC = sm + 32768;                // 16384 floats
    float* As = sm + 32768 + 16384;        // 16*TS
    float* Bs = As + 16 * TS;              // 16*TS

    int tid = threadIdx.x;
    int tx = tid & 15, ty = tid >> 4;
    int qh = blockIdx.x;                   // q-half (0/1)
    int h  = blockIdx.y;
    int b  = blockIdx.z;
    int bh = b * H_ + h;

    const float* Qp  = g_scratch + (size_t)bh * (S_ * D_);
    const float* K1p = Qp + (size_t)1 * M_ * HIDN;
    const float* K2p = Qp + (size_t)2 * M_ * HIDN;
    const float* Vp  = Qp + (size_t)3 * M_ * HIDN;
    const float* Qt  = Qp + (size_t)(qh * 128) * D_;

    float acc[8][8];

    // ---- phase 1: s1 = q @ k1^T -> P ----
    for (int jh = 0; jh < 2; jh++) {
#pragma unroll
        for (int i = 0; i < 8; i++)
#pragma unroll
            for (int j = 0; j < 8; j++) acc[i][j] = 0.f;
        for (int kt = 0; kt < 16; kt++) {
            load_tileT(As, Qt + kt * 16, D_, tid);
            load_tileT(Bs, K1p + (size_t)(jh * 128) * D_ + kt * 16, D_, tid);
            __syncthreads();
            mm16(As, Bs, acc, ty, tx);
            __syncthreads();
        }
#pragma unroll
        for (int i = 0; i < 8; i++) {
            *(float4*)(P + (ty * 8 + i) * 256 + jh * 128 + tx * 8)     = *(float4*)&acc[i][0];
            *(float4*)(P + (ty * 8 + i) * 256 + jh * 128 + tx * 8 + 4) = *(float4*)&acc[i][4];
        }
        __syncthreads();
    }

    // ---- phase 1b: scores = (s1 @ k2^T) * SCALE ----
    for (int jh = 0; jh < 2; jh++) {
#pragma unroll
        for (int i = 0; i < 8; i++)
#pragma unroll
            for (int j = 0; j < 8; j++) acc[i][j] = 0.f;
        for (int kt = 0; kt < 16; kt++) {
            load_tileT(As, P + kt * 16, 256, tid);           // A = s1 (smem)
            load_tileT(Bs, K2p + (size_t)(jh * 128) * D_ + kt * 16, D_, tid);
            __syncthreads();
            mm16(As, Bs, acc, ty, tx);
            __syncthreads();
        }
        if (jh == 0) {
            // stash half 0 in SC (s1 still needed for half 1)
#pragma unroll
            for (int i = 0; i < 8; i++) {
                float4 o0 = make_float4(acc[i][0] * SCALE_, acc[i][1] * SCALE_,
                                        acc[i][2] * SCALE_, acc[i][3] * SCALE_);
                float4 o1 = make_float4(acc[i][4] * SCALE_, acc[i][5] * SCALE_,
                                        acc[i][6] * SCALE_, acc[i][7] * SCALE_);
                *(float4*)(SC + (ty * 8 + i) * 128 + tx * 8)     = o0;
                *(float4*)(SC + (ty * 8 + i) * 128 + tx * 8 + 4) = o1;
            }
            __syncthreads();
        } else {
            // half 1 straight into P right half (s1 reads are all done)
#pragma unroll
            for (int i = 0; i < 8; i++) {
                float4 o0 = make_float4(acc[i][0] * SCALE_, acc[i][1] * SCALE_,
                                        acc[i][2] * SCALE_, acc[i][3] * SCALE_);
                float4 o1 = make_float4(acc[i][4] * SCALE_, acc[i][5] * SCALE_,
                                        acc[i][6] * SCALE_, acc[i][7] * SCALE_);
                *(float4*)(P + (ty * 8 + i) * 256 + 128 + tx * 8)     = o0;
                *(float4*)(P + (ty * 8 + i) * 256 + 128 + tx * 8 + 4) = o1;
            }
        }
    }
    // copy SC -> P left half (disjoint from right-half writes above)
#pragma unroll
    for (int it = 0; it < 16; it++) {
        int idx = tid + it * 256;                   // 4096 float4s
        int row = idx >> 5;
        int c4  = (idx & 31) << 2;
        *(float4*)(P + row * 256 + c4) = *(float4*)(SC + row * 128 + c4);
    }
    __syncthreads();

    // ---- phase 2: row softmax over cols [0, 192) ----
    {
        int warp = tid >> 5, lane = tid & 31;
        for (int q = warp; q < 128; q += 8) {
            float* row = P + q * 256;
            float m = -1e30f;
#pragma unroll
            for (int c = 0; c < 6; c++) m = fmaxf(m, row[lane + c * 32]);
#pragma unroll
            for (int o = 16; o; o >>= 1) m = fmaxf(m, __shfl_xor_sync(0xffffffffu, m, o));
            float e[6];
            float ssum = 0.f;
#pragma unroll
            for (int c = 0; c < 6; c++) { e[c] = expf(row[lane + c * 32] - m); ssum += e[c]; }
#pragma unroll
            for (int o = 16; o; o >>= 1) ssum += __shfl_xor_sync(0xffffffffu, ssum, o);
            float inv = 1.f / ssum;
#pragma unroll
            for (int c = 0; c < 6; c++) row[lane + c * 32] = e[c] * inv;
        }
    }
    __syncthreads();

    // ---- phase 3: ctx = P[:, 0:192] @ V[0:192, :] ----
    for (int dh = 0; dh < 2; dh++) {
#pragma unroll
        for (int i = 0; i < 8; i++)
#pragma unroll
            for (int j = 0; j < 8; j++) acc[i][j] = 0.f;
        for (int kt = 0; kt < 12; kt++) {          // K = 192
            load_tileT(As, P + kt * 16, 256, tid); // A = probs (smem)
            load_tileN(Bs, Vp + (size_t)(kt * 16) * D_ + dh * 128, D_, tid);
            __syncthreads();
            mm16(As, Bs, acc, ty, tx);
            __syncthreads();
        }
        // write out[b][s][h*256 + d]
#pragma unroll
        for (int i = 0; i < 8; i++) {
            int s = qh * 128 + ty * 8 + i;
            int d = dh * 128 + tx * 8;
            float* op = out + ((size_t)(b * S_ + s)) * HIDN + h * D_ + d;
            *(float4*)op       = *(float4*)&acc[i][0];
            *(float4*)(op + 4) = *(float4*)&acc[i][4];
        }
    }
}

// ---------------------------------------------------------------------------
// Launch
// ---------------------------------------------------------------------------
extern "C" void kernel_launch(void* const* d_in, const int* in_sizes, int n_in,
                              void* d_out, int out_size) {
    const float* X   = (const float*)d_in[0];
    const float* wq  = (const float*)d_in[1];
    const float* bq  = (const float*)d_in[2];
    const float* wk1 = (const float*)d_in[3];
    const float* bk1 = (const float*)d_in[4];
    const float* wk2 = (const float*)d_in[5];
    const float* bk2 = (const float*)d_in[6];
    const float* wv1 = (const float*)d_in[7];
    const float* bv1 = (const float*)d_in[8];
    const float* wv2 = (const float*)d_in[9];
    const float* bv2 = (const float*)d_in[10];
    float* out = (float*)d_out;

    const int attn_smem = (32768 + 16384 + 2 * 16 * TS) * 4;   // 213504 B
    cudaFuncSetAttribute(attn_kernel, cudaFuncAttributeMaxDynamicSharedMemorySize, attn_smem);

    combine_wv<<<(HIDN * HIDN) / 256, 256>>>(wv1, wv2, bv1, bv2);

    dim3 gproj(HIDN / 128, M_ / 128, 4);     // (32, 128, 4)
    proj_gemm<<<gproj, 256>>>(X, wq, wk1, wk2, bq, bk1, bk2);

    dim3 gattn(2, H_, B_);                   // (q-half, head, batch)
    attn_kernel<<<gattn, 256, attn_smem>>>(out);
}